// round 15
// baseline (speedup 1.0000x reference)
#include <cuda_runtime.h>
#include <cuda_fp16.h>
#include <math.h>
#include <float.h>
#include <stdint.h>

#define B_    2
#define N_    2048
#define C_    1024
#define H_    16
#define D_    64
#define HD_   1024
#define QKVC_ 3072
#define M_    (B_*N_)
#define SCALE_ 0.125f
#define LOG2E_ 1.4426950408889634f

// Scratch. v stored transposed [B,H,D,N]. q carries SCALE*LOG2E.
__device__ __half g_q[(size_t)B_*H_*N_*D_];
__device__ __half g_k[(size_t)B_*H_*N_*D_];
__device__ __half g_v[(size_t)B_*H_*D_*N_];
__device__ __half g_att[(size_t)M_*HD_];
__device__ __half g_xh[(size_t)M_*C_];
__device__ __half g_wqkvt[(size_t)QKVC_*C_];
__device__ __half g_woutt[(size_t)HD_*HD_];
__device__ __half g_qkvh[(size_t)M_*QKVC_];

// ---------------------------------------------------------------------------
__device__ __forceinline__ void mma16(float c[4], const uint32_t a[4], const uint32_t b[2]) {
    asm volatile("mma.sync.aligned.m16n8k16.row.col.f32.f16.f16.f32 "
        "{%0,%1,%2,%3},{%4,%5,%6,%7},{%8,%9},{%0,%1,%2,%3};"
        : "+f"(c[0]), "+f"(c[1]), "+f"(c[2]), "+f"(c[3])
        : "r"(a[0]), "r"(a[1]), "r"(a[2]), "r"(a[3]), "r"(b[0]), "r"(b[1]));
}
__device__ __forceinline__ uint32_t smem_u32(const void* p) {
    return (uint32_t)__cvta_generic_to_shared(p);
}
__device__ __forceinline__ void cp16(uint32_t dst, const void* src) {
    asm volatile("cp.async.cg.shared.global [%0], [%1], 16;" :: "r"(dst), "l"(src));
}
#define CP_COMMIT() asm volatile("cp.async.commit_group;" ::: "memory")
#define CP_WAIT1()  asm volatile("cp.async.wait_group 1;" ::: "memory")

__device__ __forceinline__ void ldsm_x4(uint32_t r[4], uint32_t addr) {
    asm volatile("ldmatrix.sync.aligned.m8n8.x4.shared.b16 {%0,%1,%2,%3}, [%4];"
        : "=r"(r[0]), "=r"(r[1]), "=r"(r[2]), "=r"(r[3]) : "r"(addr));
}
__device__ __forceinline__ float ex2(float x) {
    float y;
    asm("ex2.approx.f32 %0, %1;" : "=f"(y) : "f"(x));
    return y;
}
__device__ __forceinline__ uint32_t ex2_h2(float lo, float hi) {
    uint32_t x, y;
    asm("cvt.rn.f16x2.f32 %0, %1, %2;" : "=r"(x) : "f"(hi), "f"(lo));
    asm("ex2.approx.f16x2 %0, %1;" : "=r"(y) : "r"(x));
    return y;
}

// ---------------------------------------------------------------------------
// Prep (unchanged)
// ---------------------------------------------------------------------------
__global__ void conv_half(const float* __restrict__ in, __half* __restrict__ out, int n4) {
    int i = blockIdx.x * blockDim.x + threadIdx.x;
    int st = gridDim.x * blockDim.x;
    for (; i < n4; i += st) {
        float4 v = ((const float4*)in)[i];
        ((__half2*)out)[2*i]   = __floats2half2_rn(v.x, v.y);
        ((__half2*)out)[2*i+1] = __floats2half2_rn(v.z, v.w);
    }
}
__global__ void transpose_half(const float* __restrict__ in, __half* __restrict__ out,
                               int K, int N) {
    __shared__ float t[32][33];
    int bx = blockIdx.x * 32, by = blockIdx.y * 32;
    int tx = threadIdx.x, ty = threadIdx.y;
#pragma unroll
    for (int i = 0; i < 4; i++)
        t[ty + i * 8][tx] = in[(size_t)(by + ty + i * 8) * N + bx + tx];
    __syncthreads();
#pragma unroll
    for (int i = 0; i < 4; i++)
        out[(size_t)(bx + ty + i * 8) * K + by + tx] = __float2half_rn(t[tx][ty + i * 8]);
}

// ---------------------------------------------------------------------------
// fp16 TC GEMM: BK=64, 3-stage ring (unchanged from R14)
// ---------------------------------------------------------------------------
#define GS2 72
#define STG2_E (128*GS2)
#define GEMM_SMEM (3*2*STG2_E*2)

template<int NC, bool FLAT_HALF>
__global__ void __launch_bounds__(256, 2) gemm_h(const __half* __restrict__ A,
                                                 const __half* __restrict__ Bt,
                                                 void* __restrict__ outp) {
    extern __shared__ __half smg[];
    __half* As0 = smg;
    __half* Bs0 = smg + 3 * STG2_E;

    const int tid  = threadIdx.x;
    const int lane = tid & 31, warp = tid >> 5;
    const int gid  = lane >> 2, tig = lane & 3;
    const int wm   = warp & 3, wn = warp >> 2;
    const int bm   = blockIdx.y * 128, bn = blockIdx.x * 128;

    const __half* Ab = A  + (size_t)bm * 1024;
    const __half* Bb = Bt + (size_t)bn * 1024;

    auto load_tiles = [&](int kt) {
        int s = kt % 3;
        __half* As = As0 + s * STG2_E;
        __half* Bs = Bs0 + s * STG2_E;
        int k0 = kt * 64;
#pragma unroll
        for (int i = 0; i < 4; i++) {
            int e = tid + i * 256;
            int row = e >> 3, o8 = (e & 7) * 8;
            cp16(smem_u32(&As[row * GS2 + o8]), Ab + (size_t)row * 1024 + k0 + o8);
            cp16(smem_u32(&Bs[row * GS2 + o8]), Bb + (size_t)row * 1024 + k0 + o8);
        }
    };

    const int a_lr = lane & 15, a_lc = (lane >> 4) << 3;
    const int b_lr = lane & 7,  b_lc = (lane >> 3) << 3;

    float acc[2][8][4];
#pragma unroll
    for (int mi = 0; mi < 2; mi++)
#pragma unroll
        for (int ni = 0; ni < 8; ni++)
#pragma unroll
            for (int q = 0; q < 4; q++) acc[mi][ni][q] = 0.f;

    load_tiles(0); CP_COMMIT();
    load_tiles(1); CP_COMMIT();

    for (int it = 0; it < 16; it++) {
        CP_WAIT1();
        __syncthreads();
        if (it + 2 < 16) load_tiles(it + 2);
        CP_COMMIT();

        const __half* Asb = As0 + (it % 3) * STG2_E;
        const __half* Bsb = Bs0 + (it % 3) * STG2_E;

#pragma unroll
        for (int half = 0; half < 2; half++) {
            const int kk = half * 32;
            uint32_t af[2][2][4];
#pragma unroll
            for (int mi = 0; mi < 2; mi++)
#pragma unroll
                for (int kq = 0; kq < 2; kq++)
                    ldsm_x4(af[mi][kq], smem_u32(
                        &Asb[(wm * 32 + mi * 16 + a_lr) * GS2 + kk + kq * 16 + a_lc]));

#pragma unroll
            for (int ni = 0; ni < 8; ni++) {
                uint32_t bf[4];
                ldsm_x4(bf, smem_u32(&Bsb[(wn * 64 + ni * 8 + b_lr) * GS2 + kk + b_lc]));
                mma16(acc[0][ni], af[0][0], bf);
                mma16(acc[1][ni], af[1][0], bf);
                mma16(acc[0][ni], af[0][1], bf + 2);
                mma16(acc[1][ni], af[1][1], bf + 2);
            }
        }
    }

    if (FLAT_HALF) {
        __half* out = (__half*)outp;
#pragma unroll
        for (int mi = 0; mi < 2; mi++)
#pragma unroll
            for (int ni = 0; ni < 8; ni++) {
                int r = bm + wm * 32 + mi * 16 + gid;
                int c = bn + wn * 64 + ni * 8 + 2 * tig;
                *(__half2*)(out + (size_t)r * NC + c) =
                    __floats2half2_rn(acc[mi][ni][0], acc[mi][ni][1]);
                *(__half2*)(out + (size_t)(r + 8) * NC + c) =
                    __floats2half2_rn(acc[mi][ni][2], acc[mi][ni][3]);
            }
    } else {
        float* out = (float*)outp;
#pragma unroll
        for (int mi = 0; mi < 2; mi++)
#pragma unroll
            for (int ni = 0; ni < 8; ni++) {
                int r = bm + wm * 32 + mi * 16 + gid;
                int c = bn + wn * 64 + ni * 8 + 2 * tig;
                *(float2*)(out + (size_t)r * NC + c) =
                    make_float2(acc[mi][ni][0], acc[mi][ni][1]);
                *(float2*)(out + (size_t)(r + 8) * NC + c) =
                    make_float2(acc[mi][ni][2], acc[mi][ni][3]);
            }
    }
}

// ---------------------------------------------------------------------------
// Scatter (unchanged)
// ---------------------------------------------------------------------------
__global__ void __launch_bounds__(256) scatter_qkv() {
    __shared__ __half t[64 * 192];
    const int h = blockIdx.x, r0 = blockIdx.y * 64, tid = threadIdx.x;
    const __half* src = g_qkvh + (size_t)r0 * QKVC_ + h * 192;

#pragma unroll
    for (int i = 0; i < 6; i++) {
        int e = tid + i * 256;
        int row = e / 24, c8 = e % 24;
        *(float4*)&t[row * 192 + c8 * 8] =
            *(const float4*)(src + (size_t)row * QKVC_ + c8 * 8);
    }
    __syncthreads();

    const int bb = r0 >> 11;
    const int nbase = r0 & (N_ - 1);

#pragma unroll
    for (int i = 0; i < 16; i++) {
        int e = tid + i * 256;
        int s = e >> 11;
        int rem = e & 2047;
        int row = rem >> 5, d = (rem & 31) * 2;
        float v0 = __half2float(t[row * 192 + d * 3 + s]);
        float v1 = __half2float(t[row * 192 + (d + 1) * 3 + s]);
        size_t base = ((size_t)((bb * H_ + h) * N_ + nbase + row)) * D_ + d;
        if (s == 0)
            *(__half2*)(g_q + base) =
                __floats2half2_rn(v0 * (SCALE_ * LOG2E_), v1 * (SCALE_ * LOG2E_));
        else
            *(__half2*)(g_k + base) = __floats2half2_rn(v0, v1);
    }

#pragma unroll
    for (int i = 0; i < 8; i++) {
        int e = tid + i * 256;
        int d = e >> 5, n = (e & 31) * 2;
        __half v0 = t[n * 192 + d * 3 + 2];
        __half v1 = t[(n + 1) * 192 + d * 3 + 2];
        size_t base = ((size_t)((bb * H_ + h) * D_ + d)) * N_ + nbase + n;
        *(__half2*)(g_v + base) = __halves2half2(v0, v1);
    }
}

// ---------------------------------------------------------------------------
// Flash attention: R11 compute body, but K/V staged 128 keys at a time
// (16 wait+sync rounds instead of 32). 3-stage ring, occ 2.
// K stage: [128 keys][72]; V stage: [64 d][136] (keys contiguous).
// ---------------------------------------------------------------------------
#define KS_H 72
#define VT2_H 136
#define KS2_E (128*KS_H)     // 9216 halves
#define VT2_E (64*VT2_H)     // 8704 halves
#define ATTN_SMEM_BYTES ((3*(KS2_E + VT2_E))*2 + 3*128 + 128)
#define ONES2 0x3C003C00u

__global__ void __launch_bounds__(256, 2) attn_h(const float* __restrict__ pos_bias,
                                                 const unsigned char* __restrict__ mask) {
    extern __shared__ __half smh[];
    __half* Ks0 = smh;                              // 3 x [128][72]
    __half* Vt0 = smh + 3 * KS2_E;                  // 3 x [64][136]
    unsigned char* Ms0 = (unsigned char*)(Vt0 + 3 * VT2_E);   // 3 x 128

    const int tid = threadIdx.x, lane = tid & 31, wid = tid >> 5;
    const int gid = lane >> 2, tig = lane & 3;
    const int b = blockIdx.x, q0 = blockIdx.y * 128, h = blockIdx.z;
    const int bh = b * H_ + h;

    const __half* qp = g_q + (size_t)bh * N_ * D_;
    const __half* kp = g_k + (size_t)bh * N_ * D_;
    const __half* vp = g_v + (size_t)bh * D_ * N_;
    const unsigned char* maskp = mask + (size_t)b * N_;

    // load one 128-key stage
    auto loadKV = [&](int kt) {
        int s = kt % 3;
        int kk0 = kt * 128;
        __half* Ksb = Ks0 + s * KS2_E;
        __half* Vtb = Vt0 + s * VT2_E;
#pragma unroll
        for (int i = 0; i < 4; i++) {               // K: 128 rows x 64 halves
            int e = tid + i * 256;
            int row = e >> 3, o8 = (e & 7) * 8;
            cp16(smem_u32(&Ksb[row * KS_H + o8]), kp + (size_t)(kk0 + row) * D_ + o8);
        }
#pragma unroll
        for (int i = 0; i < 4; i++) {               // V: 64 rows x 128 halves
            int e = tid + i * 256;
            int row = e >> 4, o16 = (e & 15) * 8;
            cp16(smem_u32(&Vtb[row * VT2_H + o16]), vp + (size_t)row * N_ + kk0 + o16);
        }
        if (tid < 8)
            cp16(smem_u32(Ms0 + s * 128 + tid * 16), maskp + kk0 + tid * 16);
    };

    const int qrow = q0 + wid * 16 + gid;
    const __half* qh0 = qp + (size_t)qrow * D_;
    const __half* qh1 = qh0 + 8 * D_;

    uint32_t qf[4][4];
#pragma unroll
    for (int kd = 0; kd < 4; kd++) {
        qf[kd][0] = *(const uint32_t*)(qh0 + kd * 16 + 2 * tig);
        qf[kd][1] = *(const uint32_t*)(qh1 + kd * 16 + 2 * tig);
        qf[kd][2] = *(const uint32_t*)(qh0 + kd * 16 + 2 * tig + 8);
        qf[kd][3] = *(const uint32_t*)(qh1 + kd * 16 + 2 * tig + 8);
    }
    const bool qm0 = maskp[qrow] != 0, qm1 = maskp[qrow + 8] != 0;
    const bool qmask = qm0 | qm1;

    float m0 = -FLT_MAX, m1 = -FLT_MAX;
    float ol[4] = {0.f, 0.f, 0.f, 0.f};
    float of[8][4];
#pragma unroll
    for (int df = 0; df < 8; df++)
#pragma unroll
        for (int q = 0; q < 4; q++) of[df][q] = 0.f;

    const float* bias0 = pos_bias + ((size_t)h * N_ + qrow) * N_;
    const float* bias1 = bias0 + 8 * (size_t)N_;

    const int b_lr = lane & 7, b_lc = (lane >> 3) << 3;
    const uint32_t ones[2] = {ONES2, ONES2};

    loadKV(0); CP_COMMIT();
    loadKV(1); CP_COMMIT();

    for (int kt = 0; kt < N_ / 128; kt++) {         // 16 stages
        CP_WAIT1();
        __syncthreads();
        if (kt + 2 < N_ / 128) loadKV(kt + 2);
        CP_COMMIT();

        const __half* Kst = Ks0 + (kt % 3) * KS2_E;
        const __half* Vst = Vt0 + (kt % 3) * VT2_E;
        const unsigned char* Mst = Ms0 + (kt % 3) * 128;

#pragma unroll
        for (int sub = 0; sub < 2; sub++) {         // two 64-key subtiles
            const int kk0 = kt * 128 + sub * 64;
            const __half* Ksb = Kst + sub * 64 * KS_H;
            const int vcol = sub * 64;
            const unsigned char* Msb = Mst + sub * 64;

            float2 bv0[8], bv1[8];
#pragma unroll
            for (int ni = 0; ni < 8; ni++) {
                bv0[ni] = *(const float2*)(bias0 + kk0 + ni * 8 + 2 * tig);
                bv1[ni] = *(const float2*)(bias1 + kk0 + ni * 8 + 2 * tig);
            }

            const uint4* mw = (const uint4*)Msb;
            uint4 w0 = mw[0], w1 = mw[1], w2 = mw[2], w3 = mw[3];
            bool tmask = ((w0.x | w0.y | w0.z | w0.w | w1.x | w1.y | w1.z | w1.w |
                           w2.x | w2.y | w2.z | w2.w | w3.x | w3.y | w3.z | w3.w) != 0u)
                         | qmask;

            float sf[8][4];
#pragma unroll
            for (int ni = 0; ni < 8; ni++)
#pragma unroll
                for (int q = 0; q < 4; q++) sf[ni][q] = 0.f;
#pragma unroll
            for (int p = 0; p < 2; p++) {
#pragma unroll
                for (int ni = 0; ni < 8; ni++) {
                    uint32_t bq[4];
                    ldsm_x4(bq, smem_u32(&Ksb[(ni * 8 + b_lr) * KS_H + p * 32 + b_lc]));
                    mma16(sf[ni], qf[2 * p],     bq);
                    mma16(sf[ni], qf[2 * p + 1], bq + 2);
                }
            }

            float mloc0 = -FLT_MAX, mloc1 = -FLT_MAX;
            if (!tmask) {
#pragma unroll
                for (int ni = 0; ni < 8; ni++) {
                    sf[ni][0] = fmaf(bv0[ni].x, LOG2E_, sf[ni][0]);
                    sf[ni][1] = fmaf(bv0[ni].y, LOG2E_, sf[ni][1]);
                    sf[ni][2] = fmaf(bv1[ni].x, LOG2E_, sf[ni][2]);
                    sf[ni][3] = fmaf(bv1[ni].y, LOG2E_, sf[ni][3]);
                    mloc0 = fmaxf(mloc0, fmaxf(sf[ni][0], sf[ni][1]));
                    mloc1 = fmaxf(mloc1, fmaxf(sf[ni][2], sf[ni][3]));
                }
            } else {
#pragma unroll
                for (int ni = 0; ni < 8; ni++) {
                    bool km0 = Msb[ni * 8 + 2 * tig] != 0;
                    bool km1 = Msb[ni * 8 + 2 * tig + 1] != 0;
                    sf[ni][0] = (qm0 | km0) ? -FLT_MAX : fmaf(bv0[ni].x, LOG2E_, sf[ni][0]);
                    sf[ni][1] = (qm0 | km1) ? -FLT_MAX : fmaf(bv0[ni].y, LOG2E_, sf[ni][1]);
                    sf[ni][2] = (qm1 | km0) ? -FLT_MAX : fmaf(bv1[ni].x, LOG2E_, sf[ni][2]);
                    sf[ni][3] = (qm1 | km1) ? -FLT_MAX : fmaf(bv1[ni].y, LOG2E_, sf[ni][3]);
                    mloc0 = fmaxf(mloc0, fmaxf(sf[ni][0], sf[ni][1]));
                    mloc1 = fmaxf(mloc1, fmaxf(sf[ni][2], sf[ni][3]));
                }
            }
            mloc0 = fmaxf(mloc0, __shfl_xor_sync(0xffffffffu, mloc0, 1));
            mloc0 = fmaxf(mloc0, __shfl_xor_sync(0xffffffffu, mloc0, 2));
            mloc1 = fmaxf(mloc1, __shfl_xor_sync(0xffffffffu, mloc1, 1));
            mloc1 = fmaxf(mloc1, __shfl_xor_sync(0xffffffffu, mloc1, 2));

            float nm0 = fmaxf(m0, mloc0), nm1 = fmaxf(m1, mloc1);
            if ((nm0 != m0) | (nm1 != m1)) {
                float a0 = ex2(m0 - nm0), a1 = ex2(m1 - nm1);
                ol[0] *= a0; ol[1] *= a0; ol[2] *= a1; ol[3] *= a1;
#pragma unroll
                for (int df = 0; df < 8; df++) {
                    of[df][0] *= a0; of[df][1] *= a0;
                    of[df][2] *= a1; of[df][3] *= a1;
                }
                m0 = nm0; m1 = nm1;
            }

            uint32_t ph[8][2];
#pragma unroll
            for (int ni = 0; ni < 8; ni++) {
                ph[ni][0] = ex2_h2(sf[ni][0] - m0, sf[ni][1] - m0);
                ph[ni][1] = ex2_h2(sf[ni][2] - m1, sf[ni][3] - m1);
            }

#pragma unroll
            for (int p = 0; p < 2; p++) {
                uint32_t af0[4] = { ph[4*p    ][0], ph[4*p    ][1],
                                    ph[4*p + 1][0], ph[4*p + 1][1] };
                uint32_t af1[4] = { ph[4*p + 2][0], ph[4*p + 2][1],
                                    ph[4*p + 3][0], ph[4*p + 3][1] };
                mma16(ol, af0, ones);
                mma16(ol, af1, ones);
#pragma unroll
                for (int df = 0; df < 8; df++) {
                    uint32_t bq[4];
                    ldsm_x4(bq, smem_u32(&Vst[(df * 8 + b_lr) * VT2_H + vcol + p * 32 + b_lc]));
                    mma16(of[df], af0, bq);
                    mma16(of[df], af1, bq + 2);
                }
            }
        }
    }

    float inv0 = 1.f / ol[0], inv1 = 1.f / ol[2];
    __half* op0 = g_att + ((size_t)(b * N_ + qrow))     * HD_ + h * D_;
    __half* op1 = g_att + ((size_t)(b * N_ + qrow + 8)) * HD_ + h * D_;
#pragma unroll
    for (int df = 0; df < 8; df++) {
        *(__half2*)(op0 + df * 8 + 2 * tig) =
            __floats2half2_rn(of[df][0] * inv0, of[df][1] * inv0);
        *(__half2*)(op1 + df * 8 + 2 * tig) =
            __floats2half2_rn(of[df][2] * inv1, of[df][3] * inv1);
    }
}

// ---------------------------------------------------------------------------
extern "C" void kernel_launch(void* const* d_in, const int* in_sizes, int n_in,
                              void* d_out, int out_size) {
    const float*         x        = (const float*)d_in[0];
    const float*         pos_bias = (const float*)d_in[1];
    const float*         Wqkv     = (const float*)d_in[2];
    const float*         Wout     = (const float*)d_in[3];
    const unsigned char* mask     = (const unsigned char*)d_in[4];
    float*               out      = (float*)d_out;

    __half *xh, *wqkvt, *woutt, *att, *qkvh;
    cudaGetSymbolAddress((void**)&xh,    g_xh);
    cudaGetSymbolAddress((void**)&wqkvt, g_wqkvt);
    cudaGetSymbolAddress((void**)&woutt, g_woutt);
    cudaGetSymbolAddress((void**)&att,   g_att);
    cudaGetSymbolAddress((void**)&qkvh,  g_qkvh);

    conv_half<<<1024, 256>>>(x, xh, (M_ * C_) / 4);
    transpose_half<<<dim3(QKVC_/32, C_/32), dim3(32, 8)>>>(Wqkv, wqkvt, C_, QKVC_);
    transpose_half<<<dim3(HD_/32,  HD_/32), dim3(32, 8)>>>(Wout, woutt, HD_, HD_);

    cudaFuncSetAttribute(gemm_h<QKVC_, true>,
                         cudaFuncAttributeMaxDynamicSharedMemorySize, GEMM_SMEM);
    gemm_h<QKVC_, true><<<dim3(QKVC_/128, M_/128), 256, GEMM_SMEM>>>(xh, wqkvt, qkvh);

    scatter_qkv<<<dim3(H_, M_/64), 256>>>();

    cudaFuncSetAttribute(attn_h,
                         cudaFuncAttributeMaxDynamicSharedMemorySize, ATTN_SMEM_BYTES);
    attn_h<<<dim3(B_, N_/128, H_), 256, ATTN_SMEM_BYTES>>>(pos_bias, mask);

    cudaFuncSetAttribute(gemm_h<HD_, false>,
                         cudaFuncAttributeMaxDynamicSharedMemorySize, GEMM_SMEM);
    gemm_h<HD_, false><<<dim3(HD_/128, M_/128), 256, GEMM_SMEM>>>(att, woutt, out);
}

// round 16
// speedup vs baseline: 1.1205x; 1.1205x over previous
#include <cuda_runtime.h>
#include <cuda_fp16.h>
#include <math.h>
#include <float.h>
#include <stdint.h>

#define B_    2
#define N_    2048
#define C_    1024
#define H_    16
#define D_    64
#define HD_   1024
#define QKVC_ 3072
#define M_    (B_*N_)
#define SCALE_ 0.125f
#define LOG2E_ 1.4426950408889634f

// Scratch. v stored transposed [B,H,D,N]. q carries SCALE*LOG2E.
__device__ __half g_q[(size_t)B_*H_*N_*D_];
__device__ __half g_k[(size_t)B_*H_*N_*D_];
__device__ __half g_v[(size_t)B_*H_*D_*N_];
__device__ __half g_att[(size_t)M_*HD_];
__device__ __half g_xh[(size_t)M_*C_];
__device__ __half g_wqkvt[(size_t)QKVC_*C_];
__device__ __half g_woutt[(size_t)HD_*HD_];
__device__ __half g_qkvh[(size_t)M_*QKVC_];

// ---------------------------------------------------------------------------
__device__ __forceinline__ void mma16(float c[4], const uint32_t a[4], const uint32_t b[2]) {
    asm volatile("mma.sync.aligned.m16n8k16.row.col.f32.f16.f16.f32 "
        "{%0,%1,%2,%3},{%4,%5,%6,%7},{%8,%9},{%0,%1,%2,%3};"
        : "+f"(c[0]), "+f"(c[1]), "+f"(c[2]), "+f"(c[3])
        : "r"(a[0]), "r"(a[1]), "r"(a[2]), "r"(a[3]), "r"(b[0]), "r"(b[1]));
}
__device__ __forceinline__ uint32_t smem_u32(const void* p) {
    return (uint32_t)__cvta_generic_to_shared(p);
}
__device__ __forceinline__ void cp16(uint32_t dst, const void* src) {
    asm volatile("cp.async.cg.shared.global [%0], [%1], 16;" :: "r"(dst), "l"(src));
}
#define CP_COMMIT() asm volatile("cp.async.commit_group;" ::: "memory")
#define CP_WAIT0()  asm volatile("cp.async.wait_group 0;" ::: "memory")
#define CP_WAIT1()  asm volatile("cp.async.wait_group 1;" ::: "memory")

__device__ __forceinline__ void ldsm_x4(uint32_t r[4], uint32_t addr) {
    asm volatile("ldmatrix.sync.aligned.m8n8.x4.shared.b16 {%0,%1,%2,%3}, [%4];"
        : "=r"(r[0]), "=r"(r[1]), "=r"(r[2]), "=r"(r[3]) : "r"(addr));
}
__device__ __forceinline__ float ex2(float x) {
    float y;
    asm("ex2.approx.f32 %0, %1;" : "=f"(y) : "f"(x));
    return y;
}
__device__ __forceinline__ uint32_t ex2_h2(float lo, float hi) {
    uint32_t x, y;
    asm("cvt.rn.f16x2.f32 %0, %1, %2;" : "=r"(x) : "f"(hi), "f"(lo));
    asm("ex2.approx.f16x2 %0, %1;" : "=r"(y) : "r"(x));
    return y;
}

// ---------------------------------------------------------------------------
// Prep (unchanged)
// ---------------------------------------------------------------------------
__global__ void conv_half(const float* __restrict__ in, __half* __restrict__ out, int n4) {
    int i = blockIdx.x * blockDim.x + threadIdx.x;
    int st = gridDim.x * blockDim.x;
    for (; i < n4; i += st) {
        float4 v = ((const float4*)in)[i];
        ((__half2*)out)[2*i]   = __floats2half2_rn(v.x, v.y);
        ((__half2*)out)[2*i+1] = __floats2half2_rn(v.z, v.w);
    }
}
__global__ void transpose_half(const float* __restrict__ in, __half* __restrict__ out,
                               int K, int N) {
    __shared__ float t[32][33];
    int bx = blockIdx.x * 32, by = blockIdx.y * 32;
    int tx = threadIdx.x, ty = threadIdx.y;
#pragma unroll
    for (int i = 0; i < 4; i++)
        t[ty + i * 8][tx] = in[(size_t)(by + ty + i * 8) * N + bx + tx];
    __syncthreads();
#pragma unroll
    for (int i = 0; i < 4; i++)
        out[(size_t)(bx + ty + i * 8) * K + by + tx] = __float2half_rn(t[tx][ty + i * 8]);
}

// ---------------------------------------------------------------------------
// fp16 TC GEMM: BK=64, 3-stage ring (unchanged from R14)
// ---------------------------------------------------------------------------
#define GS2 72
#define STG2_E (128*GS2)
#define GEMM_SMEM (3*2*STG2_E*2)

template<int NC, bool FLAT_HALF>
__global__ void __launch_bounds__(256, 2) gemm_h(const __half* __restrict__ A,
                                                 const __half* __restrict__ Bt,
                                                 void* __restrict__ outp) {
    extern __shared__ __half smg[];
    __half* As0 = smg;
    __half* Bs0 = smg + 3 * STG2_E;

    const int tid  = threadIdx.x;
    const int lane = tid & 31, warp = tid >> 5;
    const int gid  = lane >> 2, tig = lane & 3;
    const int wm   = warp & 3, wn = warp >> 2;
    const int bm   = blockIdx.y * 128, bn = blockIdx.x * 128;

    const __half* Ab = A  + (size_t)bm * 1024;
    const __half* Bb = Bt + (size_t)bn * 1024;

    auto load_tiles = [&](int kt) {
        int s = kt % 3;
        __half* As = As0 + s * STG2_E;
        __half* Bs = Bs0 + s * STG2_E;
        int k0 = kt * 64;
#pragma unroll
        for (int i = 0; i < 4; i++) {
            int e = tid + i * 256;
            int row = e >> 3, o8 = (e & 7) * 8;
            cp16(smem_u32(&As[row * GS2 + o8]), Ab + (size_t)row * 1024 + k0 + o8);
            cp16(smem_u32(&Bs[row * GS2 + o8]), Bb + (size_t)row * 1024 + k0 + o8);
        }
    };

    const int a_lr = lane & 15, a_lc = (lane >> 4) << 3;
    const int b_lr = lane & 7,  b_lc = (lane >> 3) << 3;

    float acc[2][8][4];
#pragma unroll
    for (int mi = 0; mi < 2; mi++)
#pragma unroll
        for (int ni = 0; ni < 8; ni++)
#pragma unroll
            for (int q = 0; q < 4; q++) acc[mi][ni][q] = 0.f;

    load_tiles(0); CP_COMMIT();
    load_tiles(1); CP_COMMIT();

    for (int it = 0; it < 16; it++) {
        CP_WAIT1();
        __syncthreads();
        if (it + 2 < 16) load_tiles(it + 2);
        CP_COMMIT();

        const __half* Asb = As0 + (it % 3) * STG2_E;
        const __half* Bsb = Bs0 + (it % 3) * STG2_E;

#pragma unroll
        for (int half = 0; half < 2; half++) {
            const int kk = half * 32;
            uint32_t af[2][2][4];
#pragma unroll
            for (int mi = 0; mi < 2; mi++)
#pragma unroll
                for (int kq = 0; kq < 2; kq++)
                    ldsm_x4(af[mi][kq], smem_u32(
                        &Asb[(wm * 32 + mi * 16 + a_lr) * GS2 + kk + kq * 16 + a_lc]));

#pragma unroll
            for (int ni = 0; ni < 8; ni++) {
                uint32_t bf[4];
                ldsm_x4(bf, smem_u32(&Bsb[(wn * 64 + ni * 8 + b_lr) * GS2 + kk + b_lc]));
                mma16(acc[0][ni], af[0][0], bf);
                mma16(acc[1][ni], af[1][0], bf);
                mma16(acc[0][ni], af[0][1], bf + 2);
                mma16(acc[1][ni], af[1][1], bf + 2);
            }
        }
    }

    if (FLAT_HALF) {
        __half* out = (__half*)outp;
#pragma unroll
        for (int mi = 0; mi < 2; mi++)
#pragma unroll
            for (int ni = 0; ni < 8; ni++) {
                int r = bm + wm * 32 + mi * 16 + gid;
                int c = bn + wn * 64 + ni * 8 + 2 * tig;
                *(__half2*)(out + (size_t)r * NC + c) =
                    __floats2half2_rn(acc[mi][ni][0], acc[mi][ni][1]);
                *(__half2*)(out + (size_t)(r + 8) * NC + c) =
                    __floats2half2_rn(acc[mi][ni][2], acc[mi][ni][3]);
            }
    } else {
        float* out = (float*)outp;
#pragma unroll
        for (int mi = 0; mi < 2; mi++)
#pragma unroll
            for (int ni = 0; ni < 8; ni++) {
                int r = bm + wm * 32 + mi * 16 + gid;
                int c = bn + wn * 64 + ni * 8 + 2 * tig;
                *(float2*)(out + (size_t)r * NC + c) =
                    make_float2(acc[mi][ni][0], acc[mi][ni][1]);
                *(float2*)(out + (size_t)(r + 8) * NC + c) =
                    make_float2(acc[mi][ni][2], acc[mi][ni][3]);
            }
    }
}

// ---------------------------------------------------------------------------
// Scatter (unchanged)
// ---------------------------------------------------------------------------
__global__ void __launch_bounds__(256) scatter_qkv() {
    __shared__ __half t[64 * 192];
    const int h = blockIdx.x, r0 = blockIdx.y * 64, tid = threadIdx.x;
    const __half* src = g_qkvh + (size_t)r0 * QKVC_ + h * 192;

#pragma unroll
    for (int i = 0; i < 6; i++) {
        int e = tid + i * 256;
        int row = e / 24, c8 = e % 24;
        *(float4*)&t[row * 192 + c8 * 8] =
            *(const float4*)(src + (size_t)row * QKVC_ + c8 * 8);
    }
    __syncthreads();

    const int bb = r0 >> 11;
    const int nbase = r0 & (N_ - 1);

#pragma unroll
    for (int i = 0; i < 16; i++) {
        int e = tid + i * 256;
        int s = e >> 11;
        int rem = e & 2047;
        int row = rem >> 5, d = (rem & 31) * 2;
        float v0 = __half2float(t[row * 192 + d * 3 + s]);
        float v1 = __half2float(t[row * 192 + (d + 1) * 3 + s]);
        size_t base = ((size_t)((bb * H_ + h) * N_ + nbase + row)) * D_ + d;
        if (s == 0)
            *(__half2*)(g_q + base) =
                __floats2half2_rn(v0 * (SCALE_ * LOG2E_), v1 * (SCALE_ * LOG2E_));
        else
            *(__half2*)(g_k + base) = __floats2half2_rn(v0, v1);
    }

#pragma unroll
    for (int i = 0; i < 8; i++) {
        int e = tid + i * 256;
        int d = e >> 5, n = (e & 31) * 2;
        __half v0 = t[n * 192 + d * 3 + 2];
        __half v1 = t[(n + 1) * 192 + d * 3 + 2];
        size_t base = ((size_t)((bb * H_ + h) * D_ + d)) * N_ + nbase + n;
        *(__half2*)(g_v + base) = __halves2half2(v0, v1);
    }
}

// ---------------------------------------------------------------------------
// Flash attention — R11/R14 body, single-wave grid: 256 blocks, each CTA
// processes TWO 128-row q-tiles sequentially (grid (B, N/256, H)).
// ---------------------------------------------------------------------------
#define KS_H 72
#define VT_H 72
#define KS_E (64*KS_H)
#define VT_E (64*VT_H)
#define ATTN_SMEM_BYTES ((3*KS_E + 3*VT_E)*2 + 256)
#define ONES2 0x3C003C00u

__global__ void __launch_bounds__(256, 2) attn_h(const float* __restrict__ pos_bias,
                                                 const unsigned char* __restrict__ mask) {
    extern __shared__ __half smh[];
    __half* Ks0 = smh;
    __half* Vt0 = smh + 3 * KS_E;
    unsigned char* Ms0 = (unsigned char*)(Vt0 + 3 * VT_E);

    const int tid = threadIdx.x, lane = tid & 31, wid = tid >> 5;
    const int gid = lane >> 2, tig = lane & 3;
    const int b = blockIdx.x, h = blockIdx.z;
    const int bh = b * H_ + h;

    const __half* qp = g_q + (size_t)bh * N_ * D_;
    const __half* kp = g_k + (size_t)bh * N_ * D_;
    const __half* vp = g_v + (size_t)bh * D_ * N_;
    const unsigned char* maskp = mask + (size_t)b * N_;

    auto loadKV = [&](int kt) {
        int s = kt % 3;
        int kk0 = kt * 64;
        __half* Ksb = Ks0 + s * KS_E;
        __half* Vtb = Vt0 + s * VT_E;
#pragma unroll
        for (int i = 0; i < 2; i++) {
            int e = tid + i * 256;
            int row = e >> 3, o8 = (e & 7) * 8;
            cp16(smem_u32(&Ksb[row * KS_H + o8]), kp + (size_t)(kk0 + row) * D_ + o8);
            cp16(smem_u32(&Vtb[row * VT_H + o8]), vp + (size_t)row * N_ + kk0 + o8);
        }
        if (tid < 4)
            cp16(smem_u32(Ms0 + s * 64 + tid * 16), maskp + kk0 + tid * 16);
    };

    const int b_lr = lane & 7, b_lc = (lane >> 3) << 3;
    const uint32_t ones[2] = {ONES2, ONES2};

    for (int qt = 0; qt < 2; qt++) {
        const int q0 = blockIdx.y * 256 + qt * 128;
        const int qrow = q0 + wid * 16 + gid;
        const __half* qh0 = qp + (size_t)qrow * D_;
        const __half* qh1 = qh0 + 8 * D_;

        uint32_t qf[4][4];
#pragma unroll
        for (int kd = 0; kd < 4; kd++) {
            qf[kd][0] = *(const uint32_t*)(qh0 + kd * 16 + 2 * tig);
            qf[kd][1] = *(const uint32_t*)(qh1 + kd * 16 + 2 * tig);
            qf[kd][2] = *(const uint32_t*)(qh0 + kd * 16 + 2 * tig + 8);
            qf[kd][3] = *(const uint32_t*)(qh1 + kd * 16 + 2 * tig + 8);
        }
        const bool qm0 = maskp[qrow] != 0, qm1 = maskp[qrow + 8] != 0;
        const bool qmask = qm0 | qm1;

        float m0 = -FLT_MAX, m1 = -FLT_MAX;
        float ol[4] = {0.f, 0.f, 0.f, 0.f};
        float of[8][4];
#pragma unroll
        for (int df = 0; df < 8; df++)
#pragma unroll
            for (int q = 0; q < 4; q++) of[df][q] = 0.f;

        const float* bias0 = pos_bias + ((size_t)h * N_ + qrow) * N_;
        const float* bias1 = bias0 + 8 * (size_t)N_;

        // Quiesce ring from previous q-tile, then re-prime.
        CP_WAIT0();
        __syncthreads();
        loadKV(0); CP_COMMIT();
        loadKV(1); CP_COMMIT();

        for (int kt = 0; kt < N_ / 64; kt++) {
            const int kk0 = kt * 64;
            CP_WAIT1();
            __syncthreads();
            if (kt + 2 < N_ / 64) loadKV(kt + 2);
            CP_COMMIT();

            const __half* Ksb = Ks0 + (kt % 3) * KS_E;
            const __half* Vtb = Vt0 + (kt % 3) * VT_E;
            const unsigned char* Msb = Ms0 + (kt % 3) * 64;

            float2 bv0[8], bv1[8];
#pragma unroll
            for (int ni = 0; ni < 8; ni++) {
                bv0[ni] = *(const float2*)(bias0 + kk0 + ni * 8 + 2 * tig);
                bv1[ni] = *(const float2*)(bias1 + kk0 + ni * 8 + 2 * tig);
            }

            const uint4* mw = (const uint4*)Msb;
            uint4 w0 = mw[0], w1 = mw[1], w2 = mw[2], w3 = mw[3];
            bool tmask = ((w0.x | w0.y | w0.z | w0.w | w1.x | w1.y | w1.z | w1.w |
                           w2.x | w2.y | w2.z | w2.w | w3.x | w3.y | w3.z | w3.w) != 0u)
                         | qmask;

            float sf[8][4];
#pragma unroll
            for (int ni = 0; ni < 8; ni++)
#pragma unroll
                for (int q = 0; q < 4; q++) sf[ni][q] = 0.f;
#pragma unroll
            for (int p = 0; p < 2; p++) {
#pragma unroll
                for (int ni = 0; ni < 8; ni++) {
                    uint32_t bq[4];
                    ldsm_x4(bq, smem_u32(&Ksb[(ni * 8 + b_lr) * KS_H + p * 32 + b_lc]));
                    mma16(sf[ni], qf[2 * p],     bq);
                    mma16(sf[ni], qf[2 * p + 1], bq + 2);
                }
            }

            float mloc0 = -FLT_MAX, mloc1 = -FLT_MAX;
            if (!tmask) {
#pragma unroll
                for (int ni = 0; ni < 8; ni++) {
                    sf[ni][0] = fmaf(bv0[ni].x, LOG2E_, sf[ni][0]);
                    sf[ni][1] = fmaf(bv0[ni].y, LOG2E_, sf[ni][1]);
                    sf[ni][2] = fmaf(bv1[ni].x, LOG2E_, sf[ni][2]);
                    sf[ni][3] = fmaf(bv1[ni].y, LOG2E_, sf[ni][3]);
                    mloc0 = fmaxf(mloc0, fmaxf(sf[ni][0], sf[ni][1]));
                    mloc1 = fmaxf(mloc1, fmaxf(sf[ni][2], sf[ni][3]));
                }
            } else {
#pragma unroll
                for (int ni = 0; ni < 8; ni++) {
                    bool km0 = Msb[ni * 8 + 2 * tig] != 0;
                    bool km1 = Msb[ni * 8 + 2 * tig + 1] != 0;
                    sf[ni][0] = (qm0 | km0) ? -FLT_MAX : fmaf(bv0[ni].x, LOG2E_, sf[ni][0]);
                    sf[ni][1] = (qm0 | km1) ? -FLT_MAX : fmaf(bv0[ni].y, LOG2E_, sf[ni][1]);
                    sf[ni][2] = (qm1 | km0) ? -FLT_MAX : fmaf(bv1[ni].x, LOG2E_, sf[ni][2]);
                    sf[ni][3] = (qm1 | km1) ? -FLT_MAX : fmaf(bv1[ni].y, LOG2E_, sf[ni][3]);
                    mloc0 = fmaxf(mloc0, fmaxf(sf[ni][0], sf[ni][1]));
                    mloc1 = fmaxf(mloc1, fmaxf(sf[ni][2], sf[ni][3]));
                }
            }
            mloc0 = fmaxf(mloc0, __shfl_xor_sync(0xffffffffu, mloc0, 1));
            mloc0 = fmaxf(mloc0, __shfl_xor_sync(0xffffffffu, mloc0, 2));
            mloc1 = fmaxf(mloc1, __shfl_xor_sync(0xffffffffu, mloc1, 1));
            mloc1 = fmaxf(mloc1, __shfl_xor_sync(0xffffffffu, mloc1, 2));

            float nm0 = fmaxf(m0, mloc0), nm1 = fmaxf(m1, mloc1);
            if ((nm0 != m0) | (nm1 != m1)) {
                float a0 = ex2(m0 - nm0), a1 = ex2(m1 - nm1);
                ol[0] *= a0; ol[1] *= a0; ol[2] *= a1; ol[3] *= a1;
#pragma unroll
                for (int df = 0; df < 8; df++) {
                    of[df][0] *= a0; of[df][1] *= a0;
                    of[df][2] *= a1; of[df][3] *= a1;
                }
                m0 = nm0; m1 = nm1;
            }

            uint32_t ph[8][2];
#pragma unroll
            for (int ni = 0; ni < 8; ni++) {
                ph[ni][0] = ex2_h2(sf[ni][0] - m0, sf[ni][1] - m0);
                ph[ni][1] = ex2_h2(sf[ni][2] - m1, sf[ni][3] - m1);
            }

#pragma unroll
            for (int p = 0; p < 2; p++) {
                uint32_t af0[4] = { ph[4*p    ][0], ph[4*p    ][1],
                                    ph[4*p + 1][0], ph[4*p + 1][1] };
                uint32_t af1[4] = { ph[4*p + 2][0], ph[4*p + 2][1],
                                    ph[4*p + 3][0], ph[4*p + 3][1] };
                mma16(ol, af0, ones);
                mma16(ol, af1, ones);
#pragma unroll
                for (int df = 0; df < 8; df++) {
                    uint32_t bq[4];
                    ldsm_x4(bq, smem_u32(&Vtb[(df * 8 + b_lr) * VT_H + p * 32 + b_lc]));
                    mma16(of[df], af0, bq);
                    mma16(of[df], af1, bq + 2);
                }
            }
        }

        float inv0 = 1.f / ol[0], inv1 = 1.f / ol[2];
        __half* op0 = g_att + ((size_t)(b * N_ + qrow))     * HD_ + h * D_;
        __half* op1 = g_att + ((size_t)(b * N_ + qrow + 8)) * HD_ + h * D_;
#pragma unroll
        for (int df = 0; df < 8; df++) {
            *(__half2*)(op0 + df * 8 + 2 * tig) =
                __floats2half2_rn(of[df][0] * inv0, of[df][1] * inv0);
            *(__half2*)(op1 + df * 8 + 2 * tig) =
                __floats2half2_rn(of[df][2] * inv1, of[df][3] * inv1);
        }
    }
}

// ---------------------------------------------------------------------------
extern "C" void kernel_launch(void* const* d_in, const int* in_sizes, int n_in,
                              void* d_out, int out_size) {
    const float*         x        = (const float*)d_in[0];
    const float*         pos_bias = (const float*)d_in[1];
    const float*         Wqkv     = (const float*)d_in[2];
    const float*         Wout     = (const float*)d_in[3];
    const unsigned char* mask     = (const unsigned char*)d_in[4];
    float*               out      = (float*)d_out;

    __half *xh, *wqkvt, *woutt, *att, *qkvh;
    cudaGetSymbolAddress((void**)&xh,    g_xh);
    cudaGetSymbolAddress((void**)&wqkvt, g_wqkvt);
    cudaGetSymbolAddress((void**)&woutt, g_woutt);
    cudaGetSymbolAddress((void**)&att,   g_att);
    cudaGetSymbolAddress((void**)&qkvh,  g_qkvh);

    conv_half<<<1024, 256>>>(x, xh, (M_ * C_) / 4);
    transpose_half<<<dim3(QKVC_/32, C_/32), dim3(32, 8)>>>(Wqkv, wqkvt, C_, QKVC_);
    transpose_half<<<dim3(HD_/32,  HD_/32), dim3(32, 8)>>>(Wout, woutt, HD_, HD_);

    cudaFuncSetAttribute(gemm_h<QKVC_, true>,
                         cudaFuncAttributeMaxDynamicSharedMemorySize, GEMM_SMEM);
    gemm_h<QKVC_, true><<<dim3(QKVC_/128, M_/128), 256, GEMM_SMEM>>>(xh, wqkvt, qkvh);

    scatter_qkv<<<dim3(H_, M_/64), 256>>>();

    cudaFuncSetAttribute(attn_h,
                         cudaFuncAttributeMaxDynamicSharedMemorySize, ATTN_SMEM_BYTES);
    attn_h<<<dim3(B_, N_/256, H_), 256, ATTN_SMEM_BYTES>>>(pos_bias, mask);

    cudaFuncSetAttribute(gemm_h<HD_, false>,
                         cudaFuncAttributeMaxDynamicSharedMemorySize, GEMM_SMEM);
    gemm_h<HD_, false><<<dim3(HD_/128, M_/128), 256, GEMM_SMEM>>>(att, woutt, out);
}

// round 17
// speedup vs baseline: 1.1467x; 1.0234x over previous
#include <cuda_runtime.h>
#include <cuda_fp16.h>
#include <math.h>
#include <float.h>
#include <stdint.h>

#define B_    2
#define N_    2048
#define C_    1024
#define H_    16
#define D_    64
#define HD_   1024
#define QKVC_ 3072
#define M_    (B_*N_)
#define SCALE_ 0.125f
#define LOG2E_ 1.4426950408889634f

// Scratch. v stored transposed [B,H,D,N]. q carries SCALE*LOG2E.
__device__ __half g_q[(size_t)B_*H_*N_*D_];
__device__ __half g_k[(size_t)B_*H_*N_*D_];
__device__ __half g_v[(size_t)B_*H_*D_*N_];
__device__ __half g_att[(size_t)M_*HD_];
__device__ __half g_xh[(size_t)M_*C_];
__device__ __half g_wqkvt[(size_t)QKVC_*C_];
__device__ __half g_woutt[(size_t)HD_*HD_];
__device__ __half g_qkvh[(size_t)M_*QKVC_];

// ---------------------------------------------------------------------------
__device__ __forceinline__ void mma16(float c[4], const uint32_t a[4], const uint32_t b[2]) {
    asm volatile("mma.sync.aligned.m16n8k16.row.col.f32.f16.f16.f32 "
        "{%0,%1,%2,%3},{%4,%5,%6,%7},{%8,%9},{%0,%1,%2,%3};"
        : "+f"(c[0]), "+f"(c[1]), "+f"(c[2]), "+f"(c[3])
        : "r"(a[0]), "r"(a[1]), "r"(a[2]), "r"(a[3]), "r"(b[0]), "r"(b[1]));
}
__device__ __forceinline__ uint32_t smem_u32(const void* p) {
    return (uint32_t)__cvta_generic_to_shared(p);
}
__device__ __forceinline__ void cp16(uint32_t dst, const void* src) {
    asm volatile("cp.async.cg.shared.global [%0], [%1], 16;" :: "r"(dst), "l"(src));
}
#define CP_COMMIT() asm volatile("cp.async.commit_group;" ::: "memory")
#define CP_WAIT1()  asm volatile("cp.async.wait_group 1;" ::: "memory")

__device__ __forceinline__ void ldsm_x4(uint32_t r[4], uint32_t addr) {
    asm volatile("ldmatrix.sync.aligned.m8n8.x4.shared.b16 {%0,%1,%2,%3}, [%4];"
        : "=r"(r[0]), "=r"(r[1]), "=r"(r[2]), "=r"(r[3]) : "r"(addr));
}
__device__ __forceinline__ float ex2(float x) {
    float y;
    asm("ex2.approx.f32 %0, %1;" : "=f"(y) : "f"(x));
    return y;
}
__device__ __forceinline__ uint32_t ex2_h2(float lo, float hi) {
    uint32_t x, y;
    asm("cvt.rn.f16x2.f32 %0, %1, %2;" : "=r"(x) : "f"(hi), "f"(lo));
    asm("ex2.approx.f16x2 %0, %1;" : "=r"(y) : "r"(x));
    return y;
}

// ---------------------------------------------------------------------------
// Fused prep: z=0 conv x -> half, z=1 transpose Wqkv, z=2 transpose Wout.
// Bodies identical to the previous separate kernels (bit-identical outputs).
// ---------------------------------------------------------------------------
__global__ void prep_all(const float* __restrict__ x,    __half* __restrict__ xh,
                         const float* __restrict__ Wqkv, __half* __restrict__ wqkvt,
                         const float* __restrict__ Wout, __half* __restrict__ woutt) {
    const int tx = threadIdx.x, ty = threadIdx.y;
    if (blockIdx.z == 0) {
        // conv: grid-stride over float4s of x
        int tid = (blockIdx.y * gridDim.x + blockIdx.x) * 256 + ty * 32 + tx;
        int stride = gridDim.x * gridDim.y * 256;
        const int n4 = (M_ * C_) / 4;
        for (int i = tid; i < n4; i += stride) {
            float4 v = ((const float4*)x)[i];
            ((__half2*)xh)[2*i]   = __floats2half2_rn(v.x, v.y);
            ((__half2*)xh)[2*i+1] = __floats2half2_rn(v.z, v.w);
        }
    } else {
        const float* in = (blockIdx.z == 1) ? Wqkv : Wout;
        __half* out     = (blockIdx.z == 1) ? wqkvt : woutt;
        const int K     = (blockIdx.z == 1) ? C_ : HD_;
        const int N     = (blockIdx.z == 1) ? QKVC_ : HD_;
        int bx = blockIdx.x * 32, by = blockIdx.y * 32;
        if (bx >= N || by >= K) return;
        __shared__ float t[32][33];
#pragma unroll
        for (int i = 0; i < 4; i++)
            t[ty + i * 8][tx] = in[(size_t)(by + ty + i * 8) * N + bx + tx];
        __syncthreads();
#pragma unroll
        for (int i = 0; i < 4; i++)
            out[(size_t)(bx + ty + i * 8) * K + by + tx] = __float2half_rn(t[tx][ty + i * 8]);
    }
}

// ---------------------------------------------------------------------------
// fp16 TC GEMM: BK=64, 3-stage ring (unchanged from R14)
// ---------------------------------------------------------------------------
#define GS2 72
#define STG2_E (128*GS2)
#define GEMM_SMEM (3*2*STG2_E*2)

template<int NC, bool FLAT_HALF>
__global__ void __launch_bounds__(256, 2) gemm_h(const __half* __restrict__ A,
                                                 const __half* __restrict__ Bt,
                                                 void* __restrict__ outp) {
    extern __shared__ __half smg[];
    __half* As0 = smg;
    __half* Bs0 = smg + 3 * STG2_E;

    const int tid  = threadIdx.x;
    const int lane = tid & 31, warp = tid >> 5;
    const int gid  = lane >> 2, tig = lane & 3;
    const int wm   = warp & 3, wn = warp >> 2;
    const int bm   = blockIdx.y * 128, bn = blockIdx.x * 128;

    const __half* Ab = A  + (size_t)bm * 1024;
    const __half* Bb = Bt + (size_t)bn * 1024;

    auto load_tiles = [&](int kt) {
        int s = kt % 3;
        __half* As = As0 + s * STG2_E;
        __half* Bs = Bs0 + s * STG2_E;
        int k0 = kt * 64;
#pragma unroll
        for (int i = 0; i < 4; i++) {
            int e = tid + i * 256;
            int row = e >> 3, o8 = (e & 7) * 8;
            cp16(smem_u32(&As[row * GS2 + o8]), Ab + (size_t)row * 1024 + k0 + o8);
            cp16(smem_u32(&Bs[row * GS2 + o8]), Bb + (size_t)row * 1024 + k0 + o8);
        }
    };

    const int a_lr = lane & 15, a_lc = (lane >> 4) << 3;
    const int b_lr = lane & 7,  b_lc = (lane >> 3) << 3;

    float acc[2][8][4];
#pragma unroll
    for (int mi = 0; mi < 2; mi++)
#pragma unroll
        for (int ni = 0; ni < 8; ni++)
#pragma unroll
            for (int q = 0; q < 4; q++) acc[mi][ni][q] = 0.f;

    load_tiles(0); CP_COMMIT();
    load_tiles(1); CP_COMMIT();

    for (int it = 0; it < 16; it++) {
        CP_WAIT1();
        __syncthreads();
        if (it + 2 < 16) load_tiles(it + 2);
        CP_COMMIT();

        const __half* Asb = As0 + (it % 3) * STG2_E;
        const __half* Bsb = Bs0 + (it % 3) * STG2_E;

#pragma unroll
        for (int half = 0; half < 2; half++) {
            const int kk = half * 32;
            uint32_t af[2][2][4];
#pragma unroll
            for (int mi = 0; mi < 2; mi++)
#pragma unroll
                for (int kq = 0; kq < 2; kq++)
                    ldsm_x4(af[mi][kq], smem_u32(
                        &Asb[(wm * 32 + mi * 16 + a_lr) * GS2 + kk + kq * 16 + a_lc]));

#pragma unroll
            for (int ni = 0; ni < 8; ni++) {
                uint32_t bf[4];
                ldsm_x4(bf, smem_u32(&Bsb[(wn * 64 + ni * 8 + b_lr) * GS2 + kk + b_lc]));
                mma16(acc[0][ni], af[0][0], bf);
                mma16(acc[1][ni], af[1][0], bf);
                mma16(acc[0][ni], af[0][1], bf + 2);
                mma16(acc[1][ni], af[1][1], bf + 2);
            }
        }
    }

    if (FLAT_HALF) {
        __half* out = (__half*)outp;
#pragma unroll
        for (int mi = 0; mi < 2; mi++)
#pragma unroll
            for (int ni = 0; ni < 8; ni++) {
                int r = bm + wm * 32 + mi * 16 + gid;
                int c = bn + wn * 64 + ni * 8 + 2 * tig;
                *(__half2*)(out + (size_t)r * NC + c) =
                    __floats2half2_rn(acc[mi][ni][0], acc[mi][ni][1]);
                *(__half2*)(out + (size_t)(r + 8) * NC + c) =
                    __floats2half2_rn(acc[mi][ni][2], acc[mi][ni][3]);
            }
    } else {
        float* out = (float*)outp;
#pragma unroll
        for (int mi = 0; mi < 2; mi++)
#pragma unroll
            for (int ni = 0; ni < 8; ni++) {
                int r = bm + wm * 32 + mi * 16 + gid;
                int c = bn + wn * 64 + ni * 8 + 2 * tig;
                *(float2*)(out + (size_t)r * NC + c) =
                    make_float2(acc[mi][ni][0], acc[mi][ni][1]);
                *(float2*)(out + (size_t)(r + 8) * NC + c) =
                    make_float2(acc[mi][ni][2], acc[mi][ni][3]);
            }
    }
}

// ---------------------------------------------------------------------------
// Scatter (unchanged)
// ---------------------------------------------------------------------------
__global__ void __launch_bounds__(256) scatter_qkv() {
    __shared__ __half t[64 * 192];
    const int h = blockIdx.x, r0 = blockIdx.y * 64, tid = threadIdx.x;
    const __half* src = g_qkvh + (size_t)r0 * QKVC_ + h * 192;

#pragma unroll
    for (int i = 0; i < 6; i++) {
        int e = tid + i * 256;
        int row = e / 24, c8 = e % 24;
        *(float4*)&t[row * 192 + c8 * 8] =
            *(const float4*)(src + (size_t)row * QKVC_ + c8 * 8);
    }
    __syncthreads();

    const int bb = r0 >> 11;
    const int nbase = r0 & (N_ - 1);

#pragma unroll
    for (int i = 0; i < 16; i++) {
        int e = tid + i * 256;
        int s = e >> 11;
        int rem = e & 2047;
        int row = rem >> 5, d = (rem & 31) * 2;
        float v0 = __half2float(t[row * 192 + d * 3 + s]);
        float v1 = __half2float(t[row * 192 + (d + 1) * 3 + s]);
        size_t base = ((size_t)((bb * H_ + h) * N_ + nbase + row)) * D_ + d;
        if (s == 0)
            *(__half2*)(g_q + base) =
                __floats2half2_rn(v0 * (SCALE_ * LOG2E_), v1 * (SCALE_ * LOG2E_));
        else
            *(__half2*)(g_k + base) = __floats2half2_rn(v0, v1);
    }

#pragma unroll
    for (int i = 0; i < 8; i++) {
        int e = tid + i * 256;
        int d = e >> 5, n = (e & 31) * 2;
        __half v0 = t[n * 192 + d * 3 + 2];
        __half v1 = t[(n + 1) * 192 + d * 3 + 2];
        size_t base = ((size_t)((bb * H_ + h) * D_ + d)) * N_ + nbase + n;
        *(__half2*)(g_v + base) = __halves2half2(v0, v1);
    }
}

// ---------------------------------------------------------------------------
// Flash attention — EXACT R14 config (best known).
// ---------------------------------------------------------------------------
#define KS_H 72
#define VT_H 72
#define KS_E (64*KS_H)
#define VT_E (64*VT_H)
#define ATTN_SMEM_BYTES ((3*KS_E + 3*VT_E)*2 + 256)
#define ONES2 0x3C003C00u

__global__ void __launch_bounds__(256, 2) attn_h(const float* __restrict__ pos_bias,
                                                 const unsigned char* __restrict__ mask) {
    extern __shared__ __half smh[];
    __half* Ks0 = smh;
    __half* Vt0 = smh + 3 * KS_E;
    unsigned char* Ms0 = (unsigned char*)(Vt0 + 3 * VT_E);

    const int tid = threadIdx.x, lane = tid & 31, wid = tid >> 5;
    const int gid = lane >> 2, tig = lane & 3;
    const int b = blockIdx.x, q0 = blockIdx.y * 128, h = blockIdx.z;
    const int bh = b * H_ + h;

    const __half* qp = g_q + (size_t)bh * N_ * D_;
    const __half* kp = g_k + (size_t)bh * N_ * D_;
    const __half* vp = g_v + (size_t)bh * D_ * N_;
    const unsigned char* maskp = mask + (size_t)b * N_;

    auto loadKV = [&](int kt) {
        int s = kt % 3;
        int kk0 = kt * 64;
        __half* Ksb = Ks0 + s * KS_E;
        __half* Vtb = Vt0 + s * VT_E;
#pragma unroll
        for (int i = 0; i < 2; i++) {
            int e = tid + i * 256;
            int row = e >> 3, o8 = (e & 7) * 8;
            cp16(smem_u32(&Ksb[row * KS_H + o8]), kp + (size_t)(kk0 + row) * D_ + o8);
            cp16(smem_u32(&Vtb[row * VT_H + o8]), vp + (size_t)row * N_ + kk0 + o8);
        }
        if (tid < 4)
            cp16(smem_u32(Ms0 + s * 64 + tid * 16), maskp + kk0 + tid * 16);
    };

    const int qrow = q0 + wid * 16 + gid;
    const __half* qh0 = qp + (size_t)qrow * D_;
    const __half* qh1 = qh0 + 8 * D_;

    uint32_t qf[4][4];
#pragma unroll
    for (int kd = 0; kd < 4; kd++) {
        qf[kd][0] = *(const uint32_t*)(qh0 + kd * 16 + 2 * tig);
        qf[kd][1] = *(const uint32_t*)(qh1 + kd * 16 + 2 * tig);
        qf[kd][2] = *(const uint32_t*)(qh0 + kd * 16 + 2 * tig + 8);
        qf[kd][3] = *(const uint32_t*)(qh1 + kd * 16 + 2 * tig + 8);
    }
    const bool qm0 = maskp[qrow] != 0, qm1 = maskp[qrow + 8] != 0;
    const bool qmask = qm0 | qm1;

    float m0 = -FLT_MAX, m1 = -FLT_MAX;
    float ol[4] = {0.f, 0.f, 0.f, 0.f};
    float of[8][4];
#pragma unroll
    for (int df = 0; df < 8; df++)
#pragma unroll
        for (int q = 0; q < 4; q++) of[df][q] = 0.f;

    const float* bias0 = pos_bias + ((size_t)h * N_ + qrow) * N_;
    const float* bias1 = bias0 + 8 * (size_t)N_;

    const int b_lr = lane & 7, b_lc = (lane >> 3) << 3;
    const uint32_t ones[2] = {ONES2, ONES2};

    loadKV(0); CP_COMMIT();
    loadKV(1); CP_COMMIT();

    for (int kt = 0; kt < N_ / 64; kt++) {
        const int kk0 = kt * 64;
        CP_WAIT1();
        __syncthreads();
        if (kt + 2 < N_ / 64) loadKV(kt + 2);
        CP_COMMIT();

        const __half* Ksb = Ks0 + (kt % 3) * KS_E;
        const __half* Vtb = Vt0 + (kt % 3) * VT_E;
        const unsigned char* Msb = Ms0 + (kt % 3) * 64;

        float2 bv0[8], bv1[8];
#pragma unroll
        for (int ni = 0; ni < 8; ni++) {
            bv0[ni] = *(const float2*)(bias0 + kk0 + ni * 8 + 2 * tig);
            bv1[ni] = *(const float2*)(bias1 + kk0 + ni * 8 + 2 * tig);
        }

        const uint4* mw = (const uint4*)Msb;
        uint4 w0 = mw[0], w1 = mw[1], w2 = mw[2], w3 = mw[3];
        bool tmask = ((w0.x | w0.y | w0.z | w0.w | w1.x | w1.y | w1.z | w1.w |
                       w2.x | w2.y | w2.z | w2.w | w3.x | w3.y | w3.z | w3.w) != 0u)
                     | qmask;

        float sf[8][4];
#pragma unroll
        for (int ni = 0; ni < 8; ni++)
#pragma unroll
            for (int q = 0; q < 4; q++) sf[ni][q] = 0.f;
#pragma unroll
        for (int p = 0; p < 2; p++) {
#pragma unroll
            for (int ni = 0; ni < 8; ni++) {
                uint32_t bq[4];
                ldsm_x4(bq, smem_u32(&Ksb[(ni * 8 + b_lr) * KS_H + p * 32 + b_lc]));
                mma16(sf[ni], qf[2 * p],     bq);
                mma16(sf[ni], qf[2 * p + 1], bq + 2);
            }
        }

        float mloc0 = -FLT_MAX, mloc1 = -FLT_MAX;
        if (!tmask) {
#pragma unroll
            for (int ni = 0; ni < 8; ni++) {
                sf[ni][0] = fmaf(bv0[ni].x, LOG2E_, sf[ni][0]);
                sf[ni][1] = fmaf(bv0[ni].y, LOG2E_, sf[ni][1]);
                sf[ni][2] = fmaf(bv1[ni].x, LOG2E_, sf[ni][2]);
                sf[ni][3] = fmaf(bv1[ni].y, LOG2E_, sf[ni][3]);
                mloc0 = fmaxf(mloc0, fmaxf(sf[ni][0], sf[ni][1]));
                mloc1 = fmaxf(mloc1, fmaxf(sf[ni][2], sf[ni][3]));
            }
        } else {
#pragma unroll
            for (int ni = 0; ni < 8; ni++) {
                bool km0 = Msb[ni * 8 + 2 * tig] != 0;
                bool km1 = Msb[ni * 8 + 2 * tig + 1] != 0;
                sf[ni][0] = (qm0 | km0) ? -FLT_MAX : fmaf(bv0[ni].x, LOG2E_, sf[ni][0]);
                sf[ni][1] = (qm0 | km1) ? -FLT_MAX : fmaf(bv0[ni].y, LOG2E_, sf[ni][1]);
                sf[ni][2] = (qm1 | km0) ? -FLT_MAX : fmaf(bv1[ni].x, LOG2E_, sf[ni][2]);
                sf[ni][3] = (qm1 | km1) ? -FLT_MAX : fmaf(bv1[ni].y, LOG2E_, sf[ni][3]);
                mloc0 = fmaxf(mloc0, fmaxf(sf[ni][0], sf[ni][1]));
                mloc1 = fmaxf(mloc1, fmaxf(sf[ni][2], sf[ni][3]));
            }
        }
        mloc0 = fmaxf(mloc0, __shfl_xor_sync(0xffffffffu, mloc0, 1));
        mloc0 = fmaxf(mloc0, __shfl_xor_sync(0xffffffffu, mloc0, 2));
        mloc1 = fmaxf(mloc1, __shfl_xor_sync(0xffffffffu, mloc1, 1));
        mloc1 = fmaxf(mloc1, __shfl_xor_sync(0xffffffffu, mloc1, 2));

        float nm0 = fmaxf(m0, mloc0), nm1 = fmaxf(m1, mloc1);
        if ((nm0 != m0) | (nm1 != m1)) {
            float a0 = ex2(m0 - nm0), a1 = ex2(m1 - nm1);
            ol[0] *= a0; ol[1] *= a0; ol[2] *= a1; ol[3] *= a1;
#pragma unroll
            for (int df = 0; df < 8; df++) {
                of[df][0] *= a0; of[df][1] *= a0;
                of[df][2] *= a1; of[df][3] *= a1;
            }
            m0 = nm0; m1 = nm1;
        }

        uint32_t ph[8][2];
#pragma unroll
        for (int ni = 0; ni < 8; ni++) {
            ph[ni][0] = ex2_h2(sf[ni][0] - m0, sf[ni][1] - m0);
            ph[ni][1] = ex2_h2(sf[ni][2] - m1, sf[ni][3] - m1);
        }

#pragma unroll
        for (int p = 0; p < 2; p++) {
            uint32_t af0[4] = { ph[4*p    ][0], ph[4*p    ][1],
                                ph[4*p + 1][0], ph[4*p + 1][1] };
            uint32_t af1[4] = { ph[4*p + 2][0], ph[4*p + 2][1],
                                ph[4*p + 3][0], ph[4*p + 3][1] };
            mma16(ol, af0, ones);
            mma16(ol, af1, ones);
#pragma unroll
            for (int df = 0; df < 8; df++) {
                uint32_t bq[4];
                ldsm_x4(bq, smem_u32(&Vtb[(df * 8 + b_lr) * VT_H + p * 32 + b_lc]));
                mma16(of[df], af0, bq);
                mma16(of[df], af1, bq + 2);
            }
        }
    }

    float inv0 = 1.f / ol[0], inv1 = 1.f / ol[2];
    __half* op0 = g_att + ((size_t)(b * N_ + qrow))     * HD_ + h * D_;
    __half* op1 = g_att + ((size_t)(b * N_ + qrow + 8)) * HD_ + h * D_;
#pragma unroll
    for (int df = 0; df < 8; df++) {
        *(__half2*)(op0 + df * 8 + 2 * tig) =
            __floats2half2_rn(of[df][0] * inv0, of[df][1] * inv0);
        *(__half2*)(op1 + df * 8 + 2 * tig) =
            __floats2half2_rn(of[df][2] * inv1, of[df][3] * inv1);
    }
}

// ---------------------------------------------------------------------------
extern "C" void kernel_launch(void* const* d_in, const int* in_sizes, int n_in,
                              void* d_out, int out_size) {
    const float*         x        = (const float*)d_in[0];
    const float*         pos_bias = (const float*)d_in[1];
    const float*         Wqkv     = (const float*)d_in[2];
    const float*         Wout     = (const float*)d_in[3];
    const unsigned char* mask     = (const unsigned char*)d_in[4];
    float*               out      = (float*)d_out;

    __half *xh, *wqkvt, *woutt, *att, *qkvh;
    cudaGetSymbolAddress((void**)&xh,    g_xh);
    cudaGetSymbolAddress((void**)&wqkvt, g_wqkvt);
    cudaGetSymbolAddress((void**)&woutt, g_woutt);
    cudaGetSymbolAddress((void**)&att,   g_att);
    cudaGetSymbolAddress((void**)&qkvh,  g_qkvh);

    // Fused prep: z=0 conv x, z=1 transpose Wqkv, z=2 transpose Wout
    prep_all<<<dim3(QKVC_/32, C_/32, 3), dim3(32, 8)>>>(x, xh, Wqkv, wqkvt, Wout, woutt);

    cudaFuncSetAttribute(gemm_h<QKVC_, true>,
                         cudaFuncAttributeMaxDynamicSharedMemorySize, GEMM_SMEM);
    gemm_h<QKVC_, true><<<dim3(QKVC_/128, M_/128), 256, GEMM_SMEM>>>(xh, wqkvt, qkvh);

    scatter_qkv<<<dim3(H_, M_/64), 256>>>();

    cudaFuncSetAttribute(attn_h,
                         cudaFuncAttributeMaxDynamicSharedMemorySize, ATTN_SMEM_BYTES);
    attn_h<<<dim3(B_, N_/128, H_), 256, ATTN_SMEM_BYTES>>>(pos_bias, mask);

    cudaFuncSetAttribute(gemm_h<HD_, false>,
                         cudaFuncAttributeMaxDynamicSharedMemorySize, GEMM_SMEM);
    gemm_h<HD_, false><<<dim3(HD_/128, M_/128), 256, GEMM_SMEM>>>(att, woutt, out);
}